// round 3
// baseline (speedup 1.0000x reference)
#include <cuda_runtime.h>
#include <math.h>

#define BB 64
#define SS 128
#define HH 1024
#define GG 4096
#define VV 50257
#define TT 32
#define NPB 512   // persistent grid size (co-resident: 4/SM x 148 = 592 >= 512)

typedef unsigned long long ull;

// ---------------- scratch (device globals; no allocations) ----------------
__device__ float g_h[BB * HH];
__device__ float g_c[BB * HH];
__device__ float g_x[BB * HH];                 // decode-step input embedding
__device__ float g_part[8ull * BB * GG];       // K-split partial gate sums
__device__ float g_Xg[(size_t)SS * BB * GG];   // precomputed x@W_ih^T + b_ih + b_hh
__device__ int   g_len[BB];
__device__ float g_pv[BB * 32];
__device__ int   g_pi[BB * 32];
__device__ unsigned g_barrier_ctr;

// ---------------- f32x2 helpers (FFMA2: 2 MACs/instr on sm_103a) ----------
__device__ __forceinline__ ull ffma2(ull a, ull b, ull c) {
    ull d;
    asm("fma.rn.f32x2 %0, %1, %2, %3;" : "=l"(d) : "l"(a), "l"(b), "l"(c));
    return d;
}
__device__ __forceinline__ ull splat2(float x) {
    ull r; unsigned xi = __float_as_uint(x);
    asm("mov.b64 %0, {%1, %1};" : "=l"(r) : "r"(xi));
    return r;
}
__device__ __forceinline__ float2 unpack2(ull v) {
    unsigned lo, hi;
    asm("mov.b64 {%0, %1}, %2;" : "=r"(lo), "=r"(hi) : "l"(v));
    return make_float2(__uint_as_float(lo), __uint_as_float(hi));
}
__device__ __forceinline__ float sigmoidf_(float x) { return 1.0f / (1.0f + expf(-x)); }

// ---------------- grid-wide barrier (persistent kernels) -------------------
__device__ __forceinline__ void grid_barrier(unsigned target) {
    __threadfence();
    __syncthreads();
    if (threadIdx.x == 0) {
        atomicAdd(&g_barrier_ctr, 1u);
        while (*((volatile unsigned*)&g_barrier_ctr) < target) { }
        __threadfence();
    }
    __syncthreads();
}

// ---------------- tiny prep kernels ----------------
__global__ void k_len(const int* __restrict__ ids) {
    __shared__ int cnt[4];
    int b = blockIdx.x;
    int nz = (ids[b * SS + threadIdx.x] != 0) ? 1 : 0;
    unsigned m = __ballot_sync(0xffffffffu, nz);
    if ((threadIdx.x & 31) == 0) cnt[threadIdx.x >> 5] = __popc(m);
    __syncthreads();
    if (threadIdx.x == 0) g_len[b] = cnt[0] + cnt[1] + cnt[2] + cnt[3];
}

__global__ void k_zero() {
    int i = blockIdx.x * 256 + threadIdx.x;   // covers BB*HH
    g_h[i] = 0.0f;
    g_c[i] = 0.0f;
    if (i == 0) g_barrier_ctr = 0u;
}

// ---------------- shared 64x64 GEMM tile accumulator -----------------------
// acc[4][2]: per-thread 4(b) x 4(n) outputs, f32x2-packed along n.
__device__ __forceinline__ void gemm64x64_acc(
    float (*As)[64], float (*Ws)[64],
    const float* __restrict__ A, const float* __restrict__ W,
    int n0, int k0, int ksl, ull acc[4][2], bool ldcg_a)
{
    const int tid = threadIdx.x;
    const int tx = tid & 15, ty = tid >> 4;
    const int bo = ty * 4, jo = tx * 4;
    for (int kk = 0; kk < ksl; kk += 32) {
#pragma unroll
        for (int q0 = 0; q0 < 512; q0 += 256) {
            int q = q0 + tid;
            int r = q >> 3, kq = (q & 7) << 2;
            const float4* ap = (const float4*)(A + (size_t)r * HH + k0 + kk + kq);
            float4 v = ldcg_a ? __ldcg(ap) : *ap;
            As[kq][r] = v.x; As[kq + 1][r] = v.y; As[kq + 2][r] = v.z; As[kq + 3][r] = v.w;
            float4 w = *(const float4*)(W + (size_t)(n0 + r) * HH + k0 + kk + kq);
            Ws[kq][r] = w.x; Ws[kq + 1][r] = w.y; Ws[kq + 2][r] = w.z; Ws[kq + 3][r] = w.w;
        }
        __syncthreads();
#pragma unroll
        for (int k = 0; k < 32; k++) {
            const ull* wp = (const ull*)&Ws[k][jo];
            ull b2_0 = wp[0], b2_1 = wp[1];
            float4 a4 = *(const float4*)&As[k][bo];
            float av[4] = {a4.x, a4.y, a4.z, a4.w};
#pragma unroll
            for (int i = 0; i < 4; i++) {
                ull a2 = splat2(av[i]);
                acc[i][0] = ffma2(a2, b2_0, acc[i][0]);
                acc[i][1] = ffma2(a2, b2_1, acc[i][1]);
            }
        }
        __syncthreads();
    }
}

// ---------------- Xg = emb[ids] @ W_ih^T + b_ih + b_hh  (M=8192,N=4096,K=1024)
__global__ __launch_bounds__(256) void k_embed_gemm(
    const int* __restrict__ ids, const float* __restrict__ emb,
    const float* __restrict__ W_ih, const float* __restrict__ b_ih,
    const float* __restrict__ b_hh)
{
    __shared__ float As[16][128];  // [k][m]
    __shared__ float Bs[16][128];  // [k][n]
    __shared__ int toks[128];
    const int tid = threadIdx.x;
    const int m0 = blockIdx.y * 128;
    const int n0 = blockIdx.x * 128;
    if (tid < 128) {
        int m = m0 + tid;
        int b = m & (BB - 1);
        int s = m >> 6;
        toks[tid] = ids[b * SS + s];
    }
    __syncthreads();
    const int tx = tid & 15, ty = tid >> 4;
    const int mo = ty * 8, no = tx * 8;
    ull acc[8][4];
#pragma unroll
    for (int i = 0; i < 8; i++)
#pragma unroll
        for (int j = 0; j < 4; j++) acc[i][j] = 0ull;

    for (int k0 = 0; k0 < HH; k0 += 16) {
#pragma unroll
        for (int q0 = 0; q0 < 512; q0 += 256) {
            int q = q0 + tid;
            int r = q >> 2, kk = (q & 3) << 2;
            float4 v = *(const float4*)(emb + (size_t)toks[r] * HH + k0 + kk);
            As[kk][r] = v.x; As[kk + 1][r] = v.y; As[kk + 2][r] = v.z; As[kk + 3][r] = v.w;
            float4 w = *(const float4*)(W_ih + (size_t)(n0 + r) * HH + k0 + kk);
            Bs[kk][r] = w.x; Bs[kk + 1][r] = w.y; Bs[kk + 2][r] = w.z; Bs[kk + 3][r] = w.w;
        }
        __syncthreads();
#pragma unroll
        for (int k = 0; k < 16; k++) {
            const ull* bp = (const ull*)&Bs[k][no];
            ull b2_0 = bp[0], b2_1 = bp[1], b2_2 = bp[2], b2_3 = bp[3];
            float4 a0 = *(const float4*)&As[k][mo];
            float4 a1 = *(const float4*)&As[k][mo + 4];
            float av[8] = {a0.x, a0.y, a0.z, a0.w, a1.x, a1.y, a1.z, a1.w};
#pragma unroll
            for (int i = 0; i < 8; i++) {
                ull a2 = splat2(av[i]);
                acc[i][0] = ffma2(a2, b2_0, acc[i][0]);
                acc[i][1] = ffma2(a2, b2_1, acc[i][1]);
                acc[i][2] = ffma2(a2, b2_2, acc[i][2]);
                acc[i][3] = ffma2(a2, b2_3, acc[i][3]);
            }
        }
        __syncthreads();
    }
#pragma unroll
    for (int i = 0; i < 8; i++) {
        int m = m0 + mo + i;
        float* dst = g_Xg + (size_t)m * GG + n0 + no;
#pragma unroll
        for (int j = 0; j < 4; j++) {
            float2 cc = unpack2(acc[i][j]);
            int n = n0 + no + 2 * j;
            cc.x += b_ih[n] + b_hh[n];
            cc.y += b_ih[n + 1] + b_hh[n + 1];
            *(float2*)(dst + 2 * j) = cc;
        }
    }
}

// ---------------- fused persistent prompt recurrence -----------------------
// 512 blocks: (64 n-tiles of 64) x (8 K-slices of 128). Two grid barriers/step.
__global__ __launch_bounds__(256, 4) void k_prompt_fused(const float* __restrict__ W_hh)
{
    __shared__ float As[32][64];
    __shared__ float Ws[32][64];
    const int tid = threadIdx.x;
    const int tix = blockIdx.x;
    const int n0 = (tix >> 3) * 64;
    const int k0 = (tix & 7) * 128;
    float* outp = g_part + (size_t)(tix & 7) * (BB * GG);
    const int tx = tid & 15, ty = tid >> 4;
    const int bo = ty * 4, jo = tx * 4;
    unsigned nbar = 0;

    for (int s = 0; s < SS; s++) {
        ull acc[4][2];
#pragma unroll
        for (int i = 0; i < 4; i++) { acc[i][0] = 0ull; acc[i][1] = 0ull; }
        gemm64x64_acc(As, Ws, g_h, W_hh, n0, k0, 128, acc, true);
#pragma unroll
        for (int i = 0; i < 4; i++) {
            int b = bo + i;
            *(float2*)(outp + (size_t)b * GG + n0 + jo)     = unpack2(acc[i][0]);
            *(float2*)(outp + (size_t)b * GG + n0 + jo + 2) = unpack2(acc[i][1]);
        }
        nbar++;
        grid_barrier(nbar * NPB);

        if (tix < 256) {
            int idx = tix * 256 + tid;
            int b = idx >> 10, hc = idx & 1023;
            if (s < g_len[b]) {
                const float* xg = g_Xg + (size_t)s * BB * GG + (size_t)b * GG;
                float g4[4];
#pragma unroll
                for (int gi = 0; gi < 4; gi++) {
                    int j = gi * HH + hc;
                    float v = xg[j];
#pragma unroll
                    for (int p = 0; p < 8; p++)
                        v += __ldcg(g_part + (size_t)p * BB * GG + (size_t)b * GG + j);
                    g4[gi] = v;
                }
                float ig = sigmoidf_(g4[0]);
                float fg = sigmoidf_(g4[1]);
                float gg = tanhf(g4[2]);
                float og = sigmoidf_(g4[3]);
                float cn = fg * g_c[idx] + ig * gg;
                float hn = og * tanhf(cn);
                g_h[idx] = hn;
                g_c[idx] = cn;
            }
        }
        nbar++;
        grid_barrier(nbar * NPB);
    }
}

// ---------------- fused decode cell: both GEMMs + update, one launch -------
// blocks 0..255: g_x @ W_ih^T (K-slices of 256 -> parts 0..3)
// blocks 256..511: g_h @ W_hh^T (-> parts 4..7); then barrier; update in-place.
__global__ __launch_bounds__(256, 4) void k_decode_cell(
    const float* __restrict__ W_ih, const float* __restrict__ W_hh,
    const float* __restrict__ b_ih, const float* __restrict__ b_hh)
{
    __shared__ float As[32][64];
    __shared__ float Ws[32][64];
    const int tid = threadIdx.x;
    const int tix = blockIdx.x;
    const int half = tix >> 8;
    const int lx = tix & 255;
    const int n0 = (lx >> 2) * 64;
    const int k0 = (lx & 3) * 256;
    const float* A = half ? g_h : g_x;
    const float* W = half ? W_hh : W_ih;
    float* outp = g_part + (size_t)(half * 4 + (lx & 3)) * (BB * GG);
    const int tx = tid & 15, ty = tid >> 4;
    const int bo = ty * 4, jo = tx * 4;

    ull acc[4][2];
#pragma unroll
    for (int i = 0; i < 4; i++) { acc[i][0] = 0ull; acc[i][1] = 0ull; }
    gemm64x64_acc(As, Ws, A, W, n0, k0, 256, acc, false);
#pragma unroll
    for (int i = 0; i < 4; i++) {
        int b = bo + i;
        *(float2*)(outp + (size_t)b * GG + n0 + jo)     = unpack2(acc[i][0]);
        *(float2*)(outp + (size_t)b * GG + n0 + jo + 2) = unpack2(acc[i][1]);
    }
    grid_barrier(NPB);

    if (tix < 256) {
        int idx = tix * 256 + tid;
        int b = idx >> 10, hc = idx & 1023;
        float g4[4];
#pragma unroll
        for (int gi = 0; gi < 4; gi++) {
            int j = gi * HH + hc;
            float v = b_ih[j] + b_hh[j];
#pragma unroll
            for (int p = 0; p < 8; p++)
                v += __ldcg(g_part + (size_t)p * BB * GG + (size_t)b * GG + j);
            g4[gi] = v;
        }
        float ig = sigmoidf_(g4[0]);
        float fg = sigmoidf_(g4[1]);
        float gg = tanhf(g4[2]);
        float og = sigmoidf_(g4[3]);
        float cn = fg * g_c[idx] + ig * gg;
        float hn = og * tanhf(cn);
        g_h[idx] = hn;
        g_c[idx] = cn;
    }
}

// ---------------- logits: out[b,t,:] = h @ W_fc^T + b_fc -------------------
// tile 64(b) x 128(v), per-thread 4b x 8v, f32x2 along v.
__global__ __launch_bounds__(256) void k_logits(
    const float* __restrict__ W_fc, const float* __restrict__ b_fc,
    float* __restrict__ outbuf, int t)
{
    __shared__ float Hs[32][64];
    __shared__ float Ws2[32][128];
    const int tid = threadIdx.x;
    const int v0 = blockIdx.x * 128;
    const int ntx = tid & 15, bty = tid >> 4;
    const int bo = bty * 4, no = ntx * 8;
    ull acc[4][4];
#pragma unroll
    for (int i = 0; i < 4; i++)
#pragma unroll
        for (int j = 0; j < 4; j++) acc[i][j] = 0ull;

    for (int k0 = 0; k0 < HH; k0 += 32) {
#pragma unroll
        for (int q0 = 0; q0 < 512; q0 += 256) {
            int q = q0 + tid;
            int r = q >> 3, kq = (q & 7) << 2;
            float4 v = *(const float4*)(g_h + (size_t)r * HH + k0 + kq);
            Hs[kq][r] = v.x; Hs[kq + 1][r] = v.y; Hs[kq + 2][r] = v.z; Hs[kq + 3][r] = v.w;
        }
#pragma unroll
        for (int q0 = 0; q0 < 1024; q0 += 256) {
            int q = q0 + tid;
            int r = q >> 3, kq = (q & 7) << 2;
            float4 w = make_float4(0.f, 0.f, 0.f, 0.f);
            if (v0 + r < VV) w = *(const float4*)(W_fc + (size_t)(v0 + r) * HH + k0 + kq);
            Ws2[kq][r] = w.x; Ws2[kq + 1][r] = w.y; Ws2[kq + 2][r] = w.z; Ws2[kq + 3][r] = w.w;
        }
        __syncthreads();
#pragma unroll
        for (int k = 0; k < 32; k++) {
            const ull* wp = (const ull*)&Ws2[k][no];
            ull w0 = wp[0], w1 = wp[1], w2 = wp[2], w3 = wp[3];
            float4 a4 = *(const float4*)&Hs[k][bo];
            float av[4] = {a4.x, a4.y, a4.z, a4.w};
#pragma unroll
            for (int i = 0; i < 4; i++) {
                ull a2 = splat2(av[i]);
                acc[i][0] = ffma2(a2, w0, acc[i][0]);
                acc[i][1] = ffma2(a2, w1, acc[i][1]);
                acc[i][2] = ffma2(a2, w2, acc[i][2]);
                acc[i][3] = ffma2(a2, w3, acc[i][3]);
            }
        }
        __syncthreads();
    }
#pragma unroll
    for (int i = 0; i < 4; i++) {
        int b = bo + i;
        float* dst = outbuf + ((size_t)b * TT + t) * VV;
#pragma unroll
        for (int j = 0; j < 4; j++) {
            float2 cc = unpack2(acc[i][j]);
            int v = v0 + no + 2 * j;
            if (v < VV)     dst[v]     = cc.x + b_fc[v];
            if (v + 1 < VV) dst[v + 1] = cc.y + b_fc[v + 1];
        }
    }
}

// ---------------- argmax (first-max tie-break, matching jnp.argmax) --------
__global__ void k_argmax_part(const float* __restrict__ outbuf, int t) {
    __shared__ float sv[256];
    __shared__ int   si[256];
    int b = blockIdx.y;
    const float* row = outbuf + ((size_t)b * TT + t) * VV;
    int chunk = (VV + 31) / 32;
    int start = blockIdx.x * chunk;
    int end = min(start + chunk, VV);
    float best = -3.4e38f; int bi = VV;
    for (int v = start + threadIdx.x; v < end; v += 256) {
        float x = row[v];
        if (x > best || (x == best && v < bi)) { best = x; bi = v; }
    }
    sv[threadIdx.x] = best; si[threadIdx.x] = bi;
    __syncthreads();
    for (int st = 128; st > 0; st >>= 1) {
        if (threadIdx.x < st) {
            float o = sv[threadIdx.x + st]; int oi = si[threadIdx.x + st];
            if (o > sv[threadIdx.x] || (o == sv[threadIdx.x] && oi < si[threadIdx.x])) {
                sv[threadIdx.x] = o; si[threadIdx.x] = oi;
            }
        }
        __syncthreads();
    }
    if (threadIdx.x == 0) { g_pv[b * 32 + blockIdx.x] = sv[0]; g_pi[b * 32 + blockIdx.x] = si[0]; }
}

// also resets the grid-barrier counter for the decode-cell launch that follows
__global__ void k_argmax_fin(const float* __restrict__ emb) {
    __shared__ float sv[32];
    __shared__ int   si[32];
    __shared__ int   stok;
    int b = blockIdx.x;
    if (b == 0 && threadIdx.x == 0) g_barrier_ctr = 0u;
    if (threadIdx.x < 32) { sv[threadIdx.x] = g_pv[b * 32 + threadIdx.x]; si[threadIdx.x] = g_pi[b * 32 + threadIdx.x]; }
    __syncthreads();
    if (threadIdx.x == 0) {
        float best = sv[0]; int bi = si[0];
        for (int q = 1; q < 32; q++)
            if (sv[q] > best || (sv[q] == best && si[q] < bi)) { best = sv[q]; bi = si[q]; }
        stok = bi;
    }
    __syncthreads();
    int tok = stok;
    float4 v = *(const float4*)(emb + (size_t)tok * HH + threadIdx.x * 4);
    *(float4*)(g_x + (size_t)b * HH + threadIdx.x * 4) = v;
}

// ---------------- driver ----------------
extern "C" void kernel_launch(void* const* d_in, const int* in_sizes, int n_in,
                              void* d_out, int out_size)
{
    const int*   ids  = (const int*)d_in[0];
    // d_in[1] = max_new_tokens (fixed 32, baked into the static graph)
    const float* emb  = (const float*)d_in[2];
    const float* W_ih = (const float*)d_in[3];
    const float* W_hh = (const float*)d_in[4];
    const float* b_ih = (const float*)d_in[5];
    const float* b_hh = (const float*)d_in[6];
    const float* W_fc = (const float*)d_in[7];
    const float* b_fc = (const float*)d_in[8];
    float* out = (float*)d_out;

    k_len<<<BB, 128>>>(ids);
    k_zero<<<(BB * HH) / 256, 256>>>();

    k_embed_gemm<<<dim3(GG / 128, (BB * SS) / 128), 256>>>(ids, emb, W_ih, b_ih, b_hh);

    k_prompt_fused<<<NPB, 256>>>(W_hh);

    const int lgrid = (VV + 127) / 128;
    k_logits<<<lgrid, 256>>>(W_fc, b_fc, out, 0);

    for (int t = 1; t < TT; t++) {
        k_argmax_part<<<dim3(32, BB), 256>>>(out, t - 1);
        k_argmax_fin<<<BB, 256>>>(emb);
        k_decode_cell<<<NPB, 256>>>(W_ih, W_hh, b_ih, b_hh);
        k_logits<<<lgrid, 256>>>(W_fc, b_fc, out, t);
    }
}

// round 5
// speedup vs baseline: 1.7034x; 1.7034x over previous
#include <cuda_runtime.h>
#include <cuda_bf16.h>
#include <math.h>
#include <stdint.h>

#define BB 64
#define SS 128
#define HH 1024
#define GG 4096
#define VV 50257
#define TT 32

typedef unsigned long long ull;

// ---------------- scratch (device globals; no allocations) ----------------
__device__ float g_h[2 * BB * HH];
__device__ float g_c[2 * BB * HH];
__device__ float g_x[BB * HH];
__device__ float g_part[8ull * BB * GG];
__device__ float g_Xg[(size_t)SS * BB * GG];
__device__ int   g_len[BB];
__device__ float g_pv[BB * 32];
__device__ int   g_pi[BB * 32];
// bf16 split pairs for tensor-core logits
__device__ __nv_bfloat16 g_Whi[(size_t)VV * HH];
__device__ __nv_bfloat16 g_Wlo[(size_t)VV * HH];
__device__ __nv_bfloat16 g_hhi[BB * HH];
__device__ __nv_bfloat16 g_hlo[BB * HH];

// ---------------- f32x2 helpers ----------------
__device__ __forceinline__ ull ffma2(ull a, ull b, ull c) {
    ull d;
    asm("fma.rn.f32x2 %0, %1, %2, %3;" : "=l"(d) : "l"(a), "l"(b), "l"(c));
    return d;
}
__device__ __forceinline__ ull splat2(float x) {
    ull r; unsigned xi = __float_as_uint(x);
    asm("mov.b64 %0, {%1, %1};" : "=l"(r) : "r"(xi));
    return r;
}
__device__ __forceinline__ float2 unpack2(ull v) {
    unsigned lo, hi;
    asm("mov.b64 {%0, %1}, %2;" : "=r"(lo), "=r"(hi) : "l"(v));
    return make_float2(__uint_as_float(lo), __uint_as_float(hi));
}
__device__ __forceinline__ float sigmoidf_(float x) { return 1.0f / (1.0f + expf(-x)); }

// ---------------- mma.sync helpers (baseline PTX, no arch-suffix) ----------
__device__ __forceinline__ uint32_t smem_u32(const void* p) {
    uint32_t a;
    asm("{ .reg .u64 t; cvta.to.shared.u64 t, %1; cvt.u32.u64 %0, t; }" : "=r"(a) : "l"(p));
    return a;
}
// A-fragment: 16(m) x 16(k), row-major rows with pitch 80B
__device__ __forceinline__ void ldmA(uint32_t base, int R0, int kk0, int lane, uint32_t* a) {
    int mat = lane >> 3, ri = lane & 7;
    uint32_t addr = base + (uint32_t)(R0 + ri + ((mat & 1) << 3)) * 80u
                         + (uint32_t)((kk0 + ((mat >> 1) << 3)) << 1);
    asm volatile("ldmatrix.sync.aligned.m8n8.x4.shared.b16 {%0,%1,%2,%3}, [%4];"
        : "=r"(a[0]), "=r"(a[1]), "=r"(a[2]), "=r"(a[3]) : "r"(addr));
}
// B-fragments for two n8 blocks: rows = batch (pitch 80B), 16(k)
__device__ __forceinline__ void ldmB(uint32_t base, int N0, int kk0, int lane, uint32_t* b) {
    int mat = lane >> 3, ri = lane & 7;
    uint32_t addr = base + (uint32_t)(N0 + ri + ((mat >> 1) << 3)) * 80u
                         + (uint32_t)((kk0 + ((mat & 1) << 3)) << 1);
    asm volatile("ldmatrix.sync.aligned.m8n8.x4.shared.b16 {%0,%1,%2,%3}, [%4];"
        : "=r"(b[0]), "=r"(b[1]), "=r"(b[2]), "=r"(b[3]) : "r"(addr));
}
__device__ __forceinline__ void mma16816(float* d, const uint32_t* a, const uint32_t* b) {
    asm volatile("mma.sync.aligned.m16n8k16.row.col.f32.bf16.bf16.f32 "
        "{%0,%1,%2,%3}, {%4,%5,%6,%7}, {%8,%9}, {%0,%1,%2,%3};"
        : "+f"(d[0]), "+f"(d[1]), "+f"(d[2]), "+f"(d[3])
        : "r"(a[0]), "r"(a[1]), "r"(a[2]), "r"(a[3]), "r"(b[0]), "r"(b[1]));
}

// ---------------- tiny prep kernels ----------------
__global__ void k_len(const int* __restrict__ ids) {
    __shared__ int cnt[4];
    int b = blockIdx.x;
    int nz = (ids[b * SS + threadIdx.x] != 0) ? 1 : 0;
    unsigned m = __ballot_sync(0xffffffffu, nz);
    if ((threadIdx.x & 31) == 0) cnt[threadIdx.x >> 5] = __popc(m);
    __syncthreads();
    if (threadIdx.x == 0) g_len[b] = cnt[0] + cnt[1] + cnt[2] + cnt[3];
}

__global__ void k_zero() {
    int i = blockIdx.x * 256 + threadIdx.x;
    g_h[i] = 0.0f;
    g_c[i] = 0.0f;
}

// one-time bf16 split of W_fc
__global__ void k_wsplit(const float* __restrict__ W) {
    size_t n = (size_t)VV * HH;
    for (size_t i = (size_t)blockIdx.x * blockDim.x + threadIdx.x; i < n;
         i += (size_t)gridDim.x * blockDim.x) {
        float w = W[i];
        __nv_bfloat16 hi = __float2bfloat16(w);
        float lo = w - __bfloat162float(hi);
        g_Whi[i] = hi;
        g_Wlo[i] = __float2bfloat16(lo);
    }
}

// per-step bf16 split of h
__global__ void k_hsplit(int cur) {
    int i = blockIdx.x * 256 + threadIdx.x;
    float h = g_h[cur * (BB * HH) + i];
    __nv_bfloat16 hi = __float2bfloat16(h);
    float lo = h - __bfloat162float(hi);
    g_hhi[i] = hi;
    g_hlo[i] = __float2bfloat16(lo);
}

// ---------------- Xg = emb[ids] @ W_ih^T + b_ih + b_hh ---------------------
__global__ __launch_bounds__(256) void k_embed_gemm(
    const int* __restrict__ ids, const float* __restrict__ emb,
    const float* __restrict__ W_ih, const float* __restrict__ b_ih,
    const float* __restrict__ b_hh)
{
    __shared__ float As[16][128];
    __shared__ float Bs[16][128];
    __shared__ int toks[128];
    const int tid = threadIdx.x;
    const int m0 = blockIdx.y * 128;
    const int n0 = blockIdx.x * 128;
    if (tid < 128) {
        int m = m0 + tid;
        int b = m & (BB - 1);
        int s = m >> 6;
        toks[tid] = ids[b * SS + s];
    }
    __syncthreads();
    const int tx = tid & 15, ty = tid >> 4;
    const int mo = ty * 8, no = tx * 8;
    ull acc[8][4];
#pragma unroll
    for (int i = 0; i < 8; i++)
#pragma unroll
        for (int j = 0; j < 4; j++) acc[i][j] = 0ull;

    for (int k0 = 0; k0 < HH; k0 += 16) {
#pragma unroll
        for (int q0 = 0; q0 < 512; q0 += 256) {
            int q = q0 + tid;
            int r = q >> 2, kk = (q & 3) << 2;
            float4 v = *(const float4*)(emb + (size_t)toks[r] * HH + k0 + kk);
            As[kk][r] = v.x; As[kk + 1][r] = v.y; As[kk + 2][r] = v.z; As[kk + 3][r] = v.w;
            float4 w = *(const float4*)(W_ih + (size_t)(n0 + r) * HH + k0 + kk);
            Bs[kk][r] = w.x; Bs[kk + 1][r] = w.y; Bs[kk + 2][r] = w.z; Bs[kk + 3][r] = w.w;
        }
        __syncthreads();
#pragma unroll
        for (int k = 0; k < 16; k++) {
            const ull* bp = (const ull*)&Bs[k][no];
            ull b2_0 = bp[0], b2_1 = bp[1], b2_2 = bp[2], b2_3 = bp[3];
            float4 a0 = *(const float4*)&As[k][mo];
            float4 a1 = *(const float4*)&As[k][mo + 4];
            float av[8] = {a0.x, a0.y, a0.z, a0.w, a1.x, a1.y, a1.z, a1.w};
#pragma unroll
            for (int i = 0; i < 8; i++) {
                ull a2 = splat2(av[i]);
                acc[i][0] = ffma2(a2, b2_0, acc[i][0]);
                acc[i][1] = ffma2(a2, b2_1, acc[i][1]);
                acc[i][2] = ffma2(a2, b2_2, acc[i][2]);
                acc[i][3] = ffma2(a2, b2_3, acc[i][3]);
            }
        }
        __syncthreads();
    }
#pragma unroll
    for (int i = 0; i < 8; i++) {
        int m = m0 + mo + i;
        float* dst = g_Xg + (size_t)m * GG + n0 + no;
#pragma unroll
        for (int j = 0; j < 4; j++) {
            float2 cc = unpack2(acc[i][j]);
            int n = n0 + no + 2 * j;
            cc.x += b_ih[n] + b_hh[n];
            cc.y += b_ih[n + 1] + b_hh[n + 1];
            *(float2*)(dst + 2 * j) = cc;
        }
    }
}

// ---------------- partial gate GEMM (R2 version) ---------------------------
__global__ __launch_bounds__(256) void k_gates_part(
    int aSel, const float* __restrict__ Wt, int partBase)
{
    __shared__ float As[32][64];
    __shared__ float Ws[32][64];
    const float* A = (aSel == 2) ? g_x : (g_h + aSel * (BB * HH));
    const int tid = threadIdx.x;
    const int j0 = blockIdx.x * 64;
    const int k0 = blockIdx.y * 256;
    float* out = g_part + (size_t)(partBase + blockIdx.y) * (BB * GG);
    const int tx = tid & 15, ty = tid >> 4;
    const int bo = ty * 4, jo = tx * 4;
    ull acc[4][2];
#pragma unroll
    for (int i = 0; i < 4; i++) { acc[i][0] = 0ull; acc[i][1] = 0ull; }

    for (int kk = 0; kk < 256; kk += 32) {
#pragma unroll
        for (int q0 = 0; q0 < 512; q0 += 256) {
            int q = q0 + tid;
            int r = q >> 3, kq = (q & 7) << 2;
            float4 v = *(const float4*)(A + (size_t)r * HH + k0 + kk + kq);
            As[kq][r] = v.x; As[kq + 1][r] = v.y; As[kq + 2][r] = v.z; As[kq + 3][r] = v.w;
            float4 w = *(const float4*)(Wt + (size_t)(j0 + r) * HH + k0 + kk + kq);
            Ws[kq][r] = w.x; Ws[kq + 1][r] = w.y; Ws[kq + 2][r] = w.z; Ws[kq + 3][r] = w.w;
        }
        __syncthreads();
#pragma unroll
        for (int k = 0; k < 32; k++) {
            const ull* wp = (const ull*)&Ws[k][jo];
            ull b2_0 = wp[0], b2_1 = wp[1];
            float4 a4 = *(const float4*)&As[k][bo];
            float av[4] = {a4.x, a4.y, a4.z, a4.w};
#pragma unroll
            for (int i = 0; i < 4; i++) {
                ull a2 = splat2(av[i]);
                acc[i][0] = ffma2(a2, b2_0, acc[i][0]);
                acc[i][1] = ffma2(a2, b2_1, acc[i][1]);
            }
        }
        __syncthreads();
    }
#pragma unroll
    for (int i = 0; i < 4; i++) {
        int b = bo + i;
#pragma unroll
        for (int j = 0; j < 2; j++) {
            float2 cc = unpack2(acc[i][j]);
            *(float2*)(out + (size_t)b * GG + j0 + jo + 2 * j) = cc;
        }
    }
}

// ---------------- gate combine + state update (R2 version) -----------------
__global__ void k_update(int s, int cur, int nparts,
                         const float* __restrict__ bi, const float* __restrict__ bh)
{
    int idx = blockIdx.x * blockDim.x + threadIdx.x;
    int b = idx >> 10;
    int hc = idx & 1023;
    const float* xadd = (s >= 0) ? (g_Xg + (size_t)s * BB * GG) : nullptr;
    const float* hin = g_h + cur * (BB * HH);
    const float* cin = g_c + cur * (BB * HH);
    float* hout = g_h + (cur ^ 1) * (BB * HH);
    float* cout = g_c + (cur ^ 1) * (BB * HH);

    float g4[4];
#pragma unroll
    for (int gi = 0; gi < 4; gi++) {
        int j = gi * HH + hc;
        float v = xadd ? xadd[(size_t)b * GG + j] : (bi[j] + bh[j]);
        for (int p = 0; p < nparts; p++)
            v += g_part[(size_t)p * BB * GG + (size_t)b * GG + j];
        g4[gi] = v;
    }
    float ig = sigmoidf_(g4[0]);
    float fg = sigmoidf_(g4[1]);
    float gg = tanhf(g4[2]);
    float og = sigmoidf_(g4[3]);
    float cn = fg * cin[idx] + ig * gg;
    float hn = og * tanhf(cn);
    bool valid = (s < 0) || (s < g_len[b]);
    hout[idx] = valid ? hn : hin[idx];
    cout[idx] = valid ? cn : cin[idx];
}

// ---------------- HMMA logits: out[b,t,v] = h @ W_fc^T + b_fc --------------
// 3-term bf16 split: Whi*hhi + Whi*hlo + Wlo*hhi, fp32 accumulate.
// Block tile: 128(v) x 64(b); 8 warps 4(m) x 2(n), per-warp 32x32; BK=32.
// smem rows pitch 80B (64B data + 16B pad) for conflict-light ldmatrix.
#define SA_HI 0
#define SA_LO 10240
#define SB_HI 20480
#define SB_LO 25600
#define S_TOT 30720

__global__ __launch_bounds__(256) void k_logits_mma(
    const float* __restrict__ b_fc, float* __restrict__ outbuf, int t)
{
    __shared__ char smem[S_TOT];
    const int tid = threadIdx.x;
    const int wid = tid >> 5;
    const int lane = tid & 31;
    const int wm = wid & 3;          // m-block (32 vocab rows)
    const int wn = wid >> 2;         // n-block (32 batch cols)
    const int v0 = blockIdx.x * 128;
    const uint32_t sb = smem_u32(smem);

    float acc[2][4][4];
#pragma unroll
    for (int i = 0; i < 2; i++)
#pragma unroll
        for (int j = 0; j < 4; j++)
#pragma unroll
            for (int q = 0; q < 4; q++) acc[i][j][q] = 0.0f;

    for (int ch = 0; ch < 32; ch++) {
        const int k0 = ch * 32;
        // load A tiles: 128 rows x 32 bf16 (hi & lo), 2 uint4 per thread each
#pragma unroll
        for (int q0 = 0; q0 < 512; q0 += 256) {
            int q = q0 + tid;
            int r = q >> 2, u = q & 3;
            int v = v0 + r;
            uint4 vh = make_uint4(0, 0, 0, 0), vl = make_uint4(0, 0, 0, 0);
            if (v < VV) {
                size_t off = ((size_t)v * HH + k0) * 2 + (size_t)u * 16;
                vh = *(const uint4*)((const char*)g_Whi + off);
                vl = *(const uint4*)((const char*)g_Wlo + off);
            }
            *(uint4*)(smem + SA_HI + r * 80 + u * 16) = vh;
            *(uint4*)(smem + SA_LO + r * 80 + u * 16) = vl;
        }
        // load B tiles: 64 rows x 32 bf16 (hi & lo), 1 uint4 per thread each
        {
            int r = tid >> 2, u = tid & 3;
            size_t off = ((size_t)r * HH + k0) * 2 + (size_t)u * 16;
            *(uint4*)(smem + SB_HI + r * 80 + u * 16) = *(const uint4*)((const char*)g_hhi + off);
            *(uint4*)(smem + SB_LO + r * 80 + u * 16) = *(const uint4*)((const char*)g_hlo + off);
        }
        __syncthreads();

#pragma unroll
        for (int ks = 0; ks < 32; ks += 16) {
            uint32_t ahi[2][4], alo[2][4];
            ldmA(sb + SA_HI, wm * 32,      ks, lane, ahi[0]);
            ldmA(sb + SA_HI, wm * 32 + 16, ks, lane, ahi[1]);
            ldmA(sb + SA_LO, wm * 32,      ks, lane, alo[0]);
            ldmA(sb + SA_LO, wm * 32 + 16, ks, lane, alo[1]);
            uint32_t bhi[8], blo[8];
            ldmB(sb + SB_HI, wn * 32,      ks, lane, bhi);
            ldmB(sb + SB_HI, wn * 32 + 16, ks, lane, bhi + 4);
            ldmB(sb + SB_LO, wn * 32,      ks, lane, blo);
            ldmB(sb + SB_LO, wn * 32 + 16, ks, lane, blo + 4);
#pragma unroll
            for (int i = 0; i < 2; i++)
#pragma unroll
                for (int j = 0; j < 4; j++) {
                    mma16816(acc[i][j], ahi[i], bhi + j * 2);
                    mma16816(acc[i][j], ahi[i], blo + j * 2);
                    mma16816(acc[i][j], alo[i], bhi + j * 2);
                }
        }
        __syncthreads();
    }

    // epilogue: smem transpose (4 warps per phase), coalesced stores along v
    float* F = (float*)smem;   // 4 regions of 32x33 floats
    for (int phase = 0; phase < 2; phase++) {
        __syncthreads();
        if ((wid >> 2) == phase) {
            float* R = F + (wid & 3) * (32 * 33);
            int row = lane >> 2, cp = (lane & 3) * 2;
#pragma unroll
            for (int i = 0; i < 2; i++)
#pragma unroll
                for (int j = 0; j < 4; j++) {
                    R[(j * 8 + cp)     * 33 + i * 16 + row]     = acc[i][j][0];
                    R[(j * 8 + cp + 1) * 33 + i * 16 + row]     = acc[i][j][1];
                    R[(j * 8 + cp)     * 33 + i * 16 + row + 8] = acc[i][j][2];
                    R[(j * 8 + cp + 1) * 33 + i * 16 + row + 8] = acc[i][j][3];
                }
            __syncwarp();
            int v = v0 + wm * 32 + lane;
            if (v < VV) {
                float bias = b_fc[v];
#pragma unroll 8
                for (int bb = 0; bb < 32; bb++) {
                    int b = wn * 32 + bb;
                    outbuf[((size_t)b * TT + t) * VV + v] = R[bb * 33 + lane] + bias;
                }
            }
        }
    }
}

// ---------------- argmax (first-max tie-break) -----------------------------
__global__ void k_argmax_part(const float* __restrict__ outbuf, int t) {
    __shared__ float sv[256];
    __shared__ int   si[256];
    int b = blockIdx.y;
    const float* row = outbuf + ((size_t)b * TT + t) * VV;
    int chunk = (VV + 31) / 32;
    int start = blockIdx.x * chunk;
    int end = min(start + chunk, VV);
    float best = -3.4e38f; int bi = VV;
    for (int v = start + threadIdx.x; v < end; v += 256) {
        float x = row[v];
        if (x > best || (x == best && v < bi)) { best = x; bi = v; }
    }
    sv[threadIdx.x] = best; si[threadIdx.x] = bi;
    __syncthreads();
    for (int st = 128; st > 0; st >>= 1) {
        if (threadIdx.x < st) {
            float o = sv[threadIdx.x + st]; int oi = si[threadIdx.x + st];
            if (o > sv[threadIdx.x] || (o == sv[threadIdx.x] && oi < si[threadIdx.x])) {
                sv[threadIdx.x] = o; si[threadIdx.x] = oi;
            }
        }
        __syncthreads();
    }
    if (threadIdx.x == 0) { g_pv[b * 32 + blockIdx.x] = sv[0]; g_pi[b * 32 + blockIdx.x] = si[0]; }
}

__global__ void k_argmax_fin(const float* __restrict__ emb) {
    __shared__ float sv[32];
    __shared__ int   si[32];
    __shared__ int   stok;
    int b = blockIdx.x;
    if (threadIdx.x < 32) { sv[threadIdx.x] = g_pv[b * 32 + threadIdx.x]; si[threadIdx.x] = g_pi[b * 32 + threadIdx.x]; }
    __syncthreads();
    if (threadIdx.x == 0) {
        float best = sv[0]; int bi = si[0];
        for (int q = 1; q < 32; q++)
            if (sv[q] > best || (sv[q] == best && si[q] < bi)) { best = sv[q]; bi = si[q]; }
        stok = bi;
    }
    __syncthreads();
    int tok = stok;
    float4 v = *(const float4*)(emb + (size_t)tok * HH + threadIdx.x * 4);
    *(float4*)(g_x + (size_t)b * HH + threadIdx.x * 4) = v;
}

// ---------------- driver ----------------
extern "C" void kernel_launch(void* const* d_in, const int* in_sizes, int n_in,
                              void* d_out, int out_size)
{
    const int*   ids  = (const int*)d_in[0];
    const float* emb  = (const float*)d_in[2];
    const float* W_ih = (const float*)d_in[3];
    const float* W_hh = (const float*)d_in[4];
    const float* b_ih = (const float*)d_in[5];
    const float* b_hh = (const float*)d_in[6];
    const float* W_fc = (const float*)d_in[7];
    const float* b_fc = (const float*)d_in[8];
    float* out = (float*)d_out;

    k_len<<<BB, 128>>>(ids);
    k_zero<<<(BB * HH) / 256, 256>>>();
    k_wsplit<<<2048, 256>>>(W_fc);

    k_embed_gemm<<<dim3(GG / 128, (BB * SS) / 128), 256>>>(ids, emb, W_ih, b_ih, b_hh);

    int cur = 0;
    for (int s = 0; s < SS; s++) {
        k_gates_part<<<dim3(GG / 64, 4), 256>>>(cur, W_hh, 0);
        k_update<<<(BB * HH) / 256, 256>>>(s, cur, 4, b_ih, b_hh);
        cur ^= 1;
    }

    const int vgrid = (VV + 127) / 128;   // 393
    k_hsplit<<<(BB * HH) / 256, 256>>>(cur);
    k_logits_mma<<<vgrid, 256>>>(b_fc, out, 0);

    for (int t = 1; t < TT; t++) {
        k_argmax_part<<<dim3(32, BB), 256>>>(out, t - 1);
        k_argmax_fin<<<BB, 256>>>(emb);
        k_gates_part<<<dim3(GG / 64, 4), 256>>>(2, W_ih, 0);
        k_gates_part<<<dim3(GG / 64, 4), 256>>>(cur, W_hh, 4);
        k_update<<<(BB * HH) / 256, 256>>>(-1, cur, 8, b_ih, b_hh);
        cur ^= 1;
        k_hsplit<<<(BB * HH) / 256, 256>>>(cur);
        k_logits_mma<<<vgrid, 256>>>(b_fc, out, t);
    }
}

// round 6
// speedup vs baseline: 2.7197x; 1.5967x over previous
#include <cuda_runtime.h>
#include <cuda_bf16.h>
#include <math.h>
#include <stdint.h>

#define BB 64
#define SS 128
#define HH 1024
#define GG 4096
#define VV 50257
#define TT 32

typedef unsigned long long ull;

// ---------------- scratch (device globals; no allocations) ----------------
__device__ float g_c[BB * HH];
__device__ float g_part[8ull * BB * GG];
__device__ float g_Xg[(size_t)SS * BB * GG];
__device__ int   g_len[BB];
__device__ float g_pv[BB * 32];
__device__ int   g_pi[BB * 32];
// bf16 split pairs
__device__ __nv_bfloat16 g_Whi[(size_t)VV * HH];
__device__ __nv_bfloat16 g_Wlo[(size_t)VV * HH];
__device__ __nv_bfloat16 g_embHi[(size_t)VV * HH];
__device__ __nv_bfloat16 g_embLo[(size_t)VV * HH];
__device__ __nv_bfloat16 g_WihHi[(size_t)GG * HH];
__device__ __nv_bfloat16 g_WihLo[(size_t)GG * HH];
__device__ __nv_bfloat16 g_WhhHi[(size_t)GG * HH];
__device__ __nv_bfloat16 g_WhhLo[(size_t)GG * HH];
__device__ __nv_bfloat16 g_hhi[BB * HH];
__device__ __nv_bfloat16 g_hlo[BB * HH];
__device__ __nv_bfloat16 g_xhi[BB * HH];
__device__ __nv_bfloat16 g_xlo[BB * HH];

__device__ __forceinline__ float sigmoidf_(float x) { return 1.0f / (1.0f + expf(-x)); }

// ---------------- mma.sync helpers (validated in R5) -----------------------
__device__ __forceinline__ uint32_t smem_u32(const void* p) {
    uint32_t a;
    asm("{ .reg .u64 t; cvta.to.shared.u64 t, %1; cvt.u32.u64 %0, t; }" : "=r"(a) : "l"(p));
    return a;
}
__device__ __forceinline__ void ldmA(uint32_t base, int R0, int kk0, int lane, uint32_t* a) {
    int mat = lane >> 3, ri = lane & 7;
    uint32_t addr = base + (uint32_t)(R0 + ri + ((mat & 1) << 3)) * 80u
                         + (uint32_t)((kk0 + ((mat >> 1) << 3)) << 1);
    asm volatile("ldmatrix.sync.aligned.m8n8.x4.shared.b16 {%0,%1,%2,%3}, [%4];"
        : "=r"(a[0]), "=r"(a[1]), "=r"(a[2]), "=r"(a[3]) : "r"(addr));
}
__device__ __forceinline__ void ldmB(uint32_t base, int N0, int kk0, int lane, uint32_t* b) {
    int mat = lane >> 3, ri = lane & 7;
    uint32_t addr = base + (uint32_t)(N0 + ri + ((mat >> 1) << 3)) * 80u
                         + (uint32_t)((kk0 + ((mat & 1) << 3)) << 1);
    asm volatile("ldmatrix.sync.aligned.m8n8.x4.shared.b16 {%0,%1,%2,%3}, [%4];"
        : "=r"(b[0]), "=r"(b[1]), "=r"(b[2]), "=r"(b[3]) : "r"(addr));
}
__device__ __forceinline__ void mma16816(float* d, const uint32_t* a, const uint32_t* b) {
    asm volatile("mma.sync.aligned.m16n8k16.row.col.f32.bf16.bf16.f32 "
        "{%0,%1,%2,%3}, {%4,%5,%6,%7}, {%8,%9}, {%0,%1,%2,%3};"
        : "+f"(d[0]), "+f"(d[1]), "+f"(d[2]), "+f"(d[3])
        : "r"(a[0]), "r"(a[1]), "r"(a[2]), "r"(a[3]), "r"(b[0]), "r"(b[1]));
}

#define SA_HI 0
#define SA_LO 10240
#define SB_HI 20480
#define SB_LO 25600
#define S_TOT 30720

// shared inner machinery: loads A/B hi-lo tiles for one BK=32 chunk, runs MMAs
struct Frag { float acc[2][4][4]; };

__device__ __forceinline__ void mma_chunk(char* smem, uint32_t sb,
    const __nv_bfloat16* Ahi, const __nv_bfloat16* Alo, size_t arow0, int abound,
    const __nv_bfloat16* Bhi, const __nv_bfloat16* Blo, const int* btok,
    int k0, int tid, int lane, int wm, int wn, Frag& f)
{
#pragma unroll
    for (int q0 = 0; q0 < 512; q0 += 256) {
        int q = q0 + tid;
        int r = q >> 2, u = q & 3;
        uint4 vh = make_uint4(0, 0, 0, 0), vl = make_uint4(0, 0, 0, 0);
        if (r < abound) {
            size_t off = (arow0 + (size_t)r * HH + k0) * 2 + (size_t)u * 16;
            vh = *(const uint4*)((const char*)Ahi + off);
            vl = *(const uint4*)((const char*)Alo + off);
        }
        *(uint4*)(smem + SA_HI + r * 80 + u * 16) = vh;
        *(uint4*)(smem + SA_LO + r * 80 + u * 16) = vl;
    }
    {
        int r = tid >> 2, u = tid & 3;
        size_t row = btok ? (size_t)btok[r] : (size_t)r;
        size_t off = (row * HH + k0) * 2 + (size_t)u * 16;
        *(uint4*)(smem + SB_HI + r * 80 + u * 16) = *(const uint4*)((const char*)Bhi + off);
        *(uint4*)(smem + SB_LO + r * 80 + u * 16) = *(const uint4*)((const char*)Blo + off);
    }
    __syncthreads();
#pragma unroll
    for (int ks = 0; ks < 32; ks += 16) {
        uint32_t ahi[2][4], alo[2][4];
        ldmA(sb + SA_HI, wm * 32,      ks, lane, ahi[0]);
        ldmA(sb + SA_HI, wm * 32 + 16, ks, lane, ahi[1]);
        ldmA(sb + SA_LO, wm * 32,      ks, lane, alo[0]);
        ldmA(sb + SA_LO, wm * 32 + 16, ks, lane, alo[1]);
        uint32_t bhi[8], blo[8];
        ldmB(sb + SB_HI, wn * 32,      ks, lane, bhi);
        ldmB(sb + SB_HI, wn * 32 + 16, ks, lane, bhi + 4);
        ldmB(sb + SB_LO, wn * 32,      ks, lane, blo);
        ldmB(sb + SB_LO, wn * 32 + 16, ks, lane, blo + 4);
#pragma unroll
        for (int i = 0; i < 2; i++)
#pragma unroll
            for (int j = 0; j < 4; j++) {
                mma16816(f.acc[i][j], ahi[i], bhi + j * 2);
                mma16816(f.acc[i][j], ahi[i], blo + j * 2);
                mma16816(f.acc[i][j], alo[i], bhi + j * 2);
            }
    }
    __syncthreads();
}

// ---------------- tiny prep kernels ----------------
__global__ void k_len(const int* __restrict__ ids) {
    __shared__ int cnt[4];
    int b = blockIdx.x;
    int nz = (ids[b * SS + threadIdx.x] != 0) ? 1 : 0;
    unsigned m = __ballot_sync(0xffffffffu, nz);
    if ((threadIdx.x & 31) == 0) cnt[threadIdx.x >> 5] = __popc(m);
    __syncthreads();
    if (threadIdx.x == 0) g_len[b] = cnt[0] + cnt[1] + cnt[2] + cnt[3];
}

__global__ void k_zero() {
    int i = blockIdx.x * 256 + threadIdx.x;
    g_c[i] = 0.0f;
    g_hhi[i] = __float2bfloat16(0.0f);
    g_hlo[i] = __float2bfloat16(0.0f);
}

// bf16 split of a weight matrix (sel chooses destination globals)
__global__ void k_split(int sel, const float* __restrict__ src) {
    size_t n = (sel <= 1) ? (size_t)VV * HH : (size_t)GG * HH;
    __nv_bfloat16 *hi, *lo;
    if (sel == 0)      { hi = g_Whi;   lo = g_Wlo;   }
    else if (sel == 1) { hi = g_embHi; lo = g_embLo; }
    else if (sel == 2) { hi = g_WihHi; lo = g_WihLo; }
    else               { hi = g_WhhHi; lo = g_WhhLo; }
    for (size_t i = (size_t)blockIdx.x * blockDim.x + threadIdx.x; i < n;
         i += (size_t)gridDim.x * blockDim.x) {
        float w = src[i];
        __nv_bfloat16 h = __float2bfloat16(w);
        hi[i] = h;
        lo[i] = __float2bfloat16(w - __bfloat162float(h));
    }
}

// ---------------- HMMA embed: Xg[m, j] = emb[tok_m] @ W_ih^T + biases ------
__global__ __launch_bounds__(256) void k_embed_hmma(
    const int* __restrict__ ids, const float* __restrict__ b_ih,
    const float* __restrict__ b_hh)
{
    __shared__ char smem[S_TOT];
    __shared__ int toks[64];
    const int tid = threadIdx.x;
    const int wid = tid >> 5;
    const int lane = tid & 31;
    const int wm = wid & 3, wn = wid >> 2;
    const int j0 = blockIdx.x * 128;   // gate rows
    const int n0 = blockIdx.y * 64;    // token rows (m = s*64+b)
    const uint32_t sb = smem_u32(smem);

    if (tid < 64) {
        int m = n0 + tid;
        toks[tid] = ids[(m & 63) * SS + (m >> 6)];
    }
    __syncthreads();

    Frag f;
#pragma unroll
    for (int i = 0; i < 2; i++)
#pragma unroll
        for (int j = 0; j < 4; j++)
#pragma unroll
            for (int q = 0; q < 4; q++) f.acc[i][j][q] = 0.0f;

    for (int ch = 0; ch < 32; ch++)
        mma_chunk(smem, sb, g_WihHi, g_WihLo, (size_t)j0 * HH, 128,
                  g_embHi, g_embLo, toks, ch * 32, tid, lane, wm, wn, f);

    float* F = (float*)smem;
    for (int phase = 0; phase < 2; phase++) {
        __syncthreads();
        if ((wid >> 2) == phase) {
            float* R = F + (wid & 3) * (32 * 33);
            int row = lane >> 2, cp = (lane & 3) * 2;
#pragma unroll
            for (int i = 0; i < 2; i++)
#pragma unroll
                for (int j = 0; j < 4; j++) {
                    R[(j * 8 + cp)     * 33 + i * 16 + row]     = f.acc[i][j][0];
                    R[(j * 8 + cp + 1) * 33 + i * 16 + row]     = f.acc[i][j][1];
                    R[(j * 8 + cp)     * 33 + i * 16 + row + 8] = f.acc[i][j][2];
                    R[(j * 8 + cp + 1) * 33 + i * 16 + row + 8] = f.acc[i][j][3];
                }
            __syncwarp();
            int j = j0 + wm * 32 + lane;
            float bias = b_ih[j] + b_hh[j];
#pragma unroll 8
            for (int bb = 0; bb < 32; bb++) {
                int m = n0 + wn * 32 + bb;
                g_Xg[(size_t)m * GG + j] = R[bb * 33 + lane] + bias;
            }
        }
    }
}

// ---------------- HMMA gates: part[p][b, j] partial of A_in @ W^T ----------
// mode 0 (prompt): grid (32, 4): W_hh x h -> parts 0..3 (K-slices of 256)
// mode 1 (decode): grid (32, 8): y<4: W_ih x x -> parts 0..3; y>=4: W_hh x h -> 4..7
__global__ __launch_bounds__(256) void k_gates_hmma(int mode)
{
    __shared__ char smem[S_TOT];
    const int tid = threadIdx.x;
    const int wid = tid >> 5;
    const int lane = tid & 31;
    const int wm = wid & 3, wn = wid >> 2;
    const int j0 = blockIdx.x * 128;
    const int half = (mode == 1 && blockIdx.y >= 4) ? 1 : 0;
    const int kslot = blockIdx.y & 3;
    const int kq0 = kslot * 256;
    const __nv_bfloat16* Ahi;
    const __nv_bfloat16* Alo;
    const __nv_bfloat16* Bhi;
    const __nv_bfloat16* Blo;
    if (mode == 0 || half == 1) { Ahi = g_WhhHi; Alo = g_WhhLo; Bhi = g_hhi; Blo = g_hlo; }
    else                        { Ahi = g_WihHi; Alo = g_WihLo; Bhi = g_xhi; Blo = g_xlo; }
    const int part = (mode == 0) ? kslot : (half * 4 + kslot);
    float* out = g_part + (size_t)part * (BB * GG);
    const uint32_t sb = smem_u32(smem);

    Frag f;
#pragma unroll
    for (int i = 0; i < 2; i++)
#pragma unroll
        for (int j = 0; j < 4; j++)
#pragma unroll
            for (int q = 0; q < 4; q++) f.acc[i][j][q] = 0.0f;

    for (int ch = 0; ch < 8; ch++)
        mma_chunk(smem, sb, Ahi, Alo, (size_t)j0 * HH, 128,
                  Bhi, Blo, nullptr, kq0 + ch * 32, tid, lane, wm, wn, f);

    float* F = (float*)smem;
    for (int phase = 0; phase < 2; phase++) {
        __syncthreads();
        if ((wid >> 2) == phase) {
            float* R = F + (wid & 3) * (32 * 33);
            int row = lane >> 2, cp = (lane & 3) * 2;
#pragma unroll
            for (int i = 0; i < 2; i++)
#pragma unroll
                for (int j = 0; j < 4; j++) {
                    R[(j * 8 + cp)     * 33 + i * 16 + row]     = f.acc[i][j][0];
                    R[(j * 8 + cp + 1) * 33 + i * 16 + row]     = f.acc[i][j][1];
                    R[(j * 8 + cp)     * 33 + i * 16 + row + 8] = f.acc[i][j][2];
                    R[(j * 8 + cp + 1) * 33 + i * 16 + row + 8] = f.acc[i][j][3];
                }
            __syncwarp();
            int j = j0 + wm * 32 + lane;
#pragma unroll 8
            for (int bb = 0; bb < 32; bb++) {
                int b = wn * 32 + bb;
                out[(size_t)b * GG + j] = R[bb * 33 + lane];
            }
        }
    }
}

// ---------------- gate combine + state update ------------------------------
// in-place h (as bf16 split pair) and c; s>=0 prompt masked, s<0 decode.
__global__ void k_update(int s, int nparts,
                         const float* __restrict__ bi, const float* __restrict__ bh)
{
    int idx = blockIdx.x * blockDim.x + threadIdx.x;
    int b = idx >> 10;
    int hc = idx & 1023;
    bool valid = (s < 0) || (s < g_len[b]);
    if (!valid) return;
    const float* xadd = (s >= 0) ? (g_Xg + (size_t)s * BB * GG) : nullptr;

    float g4[4];
#pragma unroll
    for (int gi = 0; gi < 4; gi++) {
        int j = gi * HH + hc;
        float v = xadd ? xadd[(size_t)b * GG + j] : (bi[j] + bh[j]);
#pragma unroll
        for (int p = 0; p < 8; p++)
            if (p < nparts) v += g_part[(size_t)p * BB * GG + (size_t)b * GG + j];
        g4[gi] = v;
    }
    float ig = sigmoidf_(g4[0]);
    float fg = sigmoidf_(g4[1]);
    float gg = tanhf(g4[2]);
    float og = sigmoidf_(g4[3]);
    float cn = fg * g_c[idx] + ig * gg;
    float hn = og * tanhf(cn);
    g_c[idx] = cn;
    __nv_bfloat16 hi = __float2bfloat16(hn);
    g_hhi[idx] = hi;
    g_hlo[idx] = __float2bfloat16(hn - __bfloat162float(hi));
}

// ---------------- HMMA logits (validated R5) -------------------------------
__global__ __launch_bounds__(256) void k_logits_mma(
    const float* __restrict__ b_fc, float* __restrict__ outbuf, int t)
{
    __shared__ char smem[S_TOT];
    const int tid = threadIdx.x;
    const int wid = tid >> 5;
    const int lane = tid & 31;
    const int wm = wid & 3, wn = wid >> 2;
    const int v0 = blockIdx.x * 128;
    const uint32_t sb = smem_u32(smem);

    Frag f;
#pragma unroll
    for (int i = 0; i < 2; i++)
#pragma unroll
        for (int j = 0; j < 4; j++)
#pragma unroll
            for (int q = 0; q < 4; q++) f.acc[i][j][q] = 0.0f;

    const int abound = min(128, VV - v0);
    for (int ch = 0; ch < 32; ch++)
        mma_chunk(smem, sb, g_Whi, g_Wlo, (size_t)v0 * HH, abound,
                  g_hhi, g_hlo, nullptr, ch * 32, tid, lane, wm, wn, f);

    float* F = (float*)smem;
    for (int phase = 0; phase < 2; phase++) {
        __syncthreads();
        if ((wid >> 2) == phase) {
            float* R = F + (wid & 3) * (32 * 33);
            int row = lane >> 2, cp = (lane & 3) * 2;
#pragma unroll
            for (int i = 0; i < 2; i++)
#pragma unroll
                for (int j = 0; j < 4; j++) {
                    R[(j * 8 + cp)     * 33 + i * 16 + row]     = f.acc[i][j][0];
                    R[(j * 8 + cp + 1) * 33 + i * 16 + row]     = f.acc[i][j][1];
                    R[(j * 8 + cp)     * 33 + i * 16 + row + 8] = f.acc[i][j][2];
                    R[(j * 8 + cp + 1) * 33 + i * 16 + row + 8] = f.acc[i][j][3];
                }
            __syncwarp();
            int v = v0 + wm * 32 + lane;
            if (v < VV) {
                float bias = b_fc[v];
#pragma unroll 8
                for (int bb = 0; bb < 32; bb++) {
                    int b = wn * 32 + bb;
                    outbuf[((size_t)b * TT + t) * VV + v] = R[bb * 33 + lane] + bias;
                }
            }
        }
    }
}

// ---------------- argmax (first-max tie-break) -----------------------------
__global__ void k_argmax_part(const float* __restrict__ outbuf, int t) {
    __shared__ float sv[256];
    __shared__ int   si[256];
    int b = blockIdx.y;
    const float* row = outbuf + ((size_t)b * TT + t) * VV;
    int chunk = (VV + 31) / 32;
    int start = blockIdx.x * chunk;
    int end = min(start + chunk, VV);
    float best = -3.4e38f; int bi = VV;
    for (int v = start + threadIdx.x; v < end; v += 256) {
        float x = row[v];
        if (x > best || (x == best && v < bi)) { best = x; bi = v; }
    }
    sv[threadIdx.x] = best; si[threadIdx.x] = bi;
    __syncthreads();
    for (int st = 128; st > 0; st >>= 1) {
        if (threadIdx.x < st) {
            float o = sv[threadIdx.x + st]; int oi = si[threadIdx.x + st];
            if (o > sv[threadIdx.x] || (o == sv[threadIdx.x] && oi < si[threadIdx.x])) {
                sv[threadIdx.x] = o; si[threadIdx.x] = oi;
            }
        }
        __syncthreads();
    }
    if (threadIdx.x == 0) { g_pv[b * 32 + blockIdx.x] = sv[0]; g_pi[b * 32 + blockIdx.x] = si[0]; }
}

// final argmax; writes x split pair (copy of pre-split emb rows)
__global__ void k_argmax_fin() {
    __shared__ float sv[32];
    __shared__ int   si[32];
    __shared__ int   stok;
    int b = blockIdx.x;
    if (threadIdx.x < 32) { sv[threadIdx.x] = g_pv[b * 32 + threadIdx.x]; si[threadIdx.x] = g_pi[b * 32 + threadIdx.x]; }
    __syncthreads();
    if (threadIdx.x == 0) {
        float best = sv[0]; int bi = si[0];
        for (int q = 1; q < 32; q++)
            if (sv[q] > best || (sv[q] == best && si[q] < bi)) { best = sv[q]; bi = si[q]; }
        stok = bi;
    }
    __syncthreads();
    size_t tok = (size_t)stok;
    ((uint2*)(g_xhi + (size_t)b * HH))[threadIdx.x] = ((const uint2*)(g_embHi + tok * HH))[threadIdx.x];
    ((uint2*)(g_xlo + (size_t)b * HH))[threadIdx.x] = ((const uint2*)(g_embLo + tok * HH))[threadIdx.x];
}

// ---------------- driver ----------------
extern "C" void kernel_launch(void* const* d_in, const int* in_sizes, int n_in,
                              void* d_out, int out_size)
{
    const int*   ids  = (const int*)d_in[0];
    const float* emb  = (const float*)d_in[2];
    const float* W_ih = (const float*)d_in[3];
    const float* W_hh = (const float*)d_in[4];
    const float* b_ih = (const float*)d_in[5];
    const float* b_hh = (const float*)d_in[6];
    const float* W_fc = (const float*)d_in[7];
    const float* b_fc = (const float*)d_in[8];
    float* out = (float*)d_out;

    k_len<<<BB, 128>>>(ids);
    k_zero<<<(BB * HH) / 256, 256>>>();
    k_split<<<2048, 256>>>(0, W_fc);
    k_split<<<2048, 256>>>(1, emb);
    k_split<<<512, 256>>>(2, W_ih);
    k_split<<<512, 256>>>(3, W_hh);

    k_embed_hmma<<<dim3(GG / 128, (BB * SS) / 64), 256>>>(ids, b_ih, b_hh);

    for (int s = 0; s < SS; s++) {
        k_gates_hmma<<<dim3(32, 4), 256>>>(0);
        k_update<<<(BB * HH) / 256, 256>>>(s, 4, b_ih, b_hh);
    }

    const int vgrid = (VV + 127) / 128;   // 393
    k_logits_mma<<<vgrid, 256>>>(b_fc, out, 0);

    for (int t = 1; t < TT; t++) {
        k_argmax_part<<<dim3(32, BB), 256>>>(out, t - 1);
        k_argmax_fin<<<BB, 256>>>();
        k_gates_hmma<<<dim3(32, 8), 256>>>(1);
        k_update<<<(BB * HH) / 256, 256>>>(-1, 8, b_ih, b_hh);
        k_logits_mma<<<vgrid, 256>>>(b_fc, out, t);
    }
}

// round 7
// speedup vs baseline: 2.9238x; 1.0750x over previous
#include <cuda_runtime.h>
#include <cuda_bf16.h>
#include <math.h>
#include <stdint.h>

#define BB 64
#define SS 128
#define HH 1024
#define GG 4096
#define VV 50257
#define VP 50304   // padded vocab rows for guard-free A tiles
#define TT 32

typedef unsigned long long ull;

// ---------------- scratch (device globals; no allocations) ----------------
__device__ float g_c[BB * HH];
__device__ float g_part[8ull * BB * GG];
__device__ float g_Xg[(size_t)SS * BB * GG];
__device__ int   g_len[BB];
__device__ float g_pv[BB * 32];
__device__ int   g_pi[BB * 32];
// bf16 split pairs
__device__ __nv_bfloat16 g_Whi[(size_t)VP * HH];
__device__ __nv_bfloat16 g_Wlo[(size_t)VP * HH];
__device__ __nv_bfloat16 g_embHi[(size_t)VV * HH];
__device__ __nv_bfloat16 g_embLo[(size_t)VV * HH];
__device__ __nv_bfloat16 g_WihHi[(size_t)GG * HH];
__device__ __nv_bfloat16 g_WihLo[(size_t)GG * HH];
__device__ __nv_bfloat16 g_WhhHi[(size_t)GG * HH];
__device__ __nv_bfloat16 g_WhhLo[(size_t)GG * HH];
__device__ __nv_bfloat16 g_hhi[BB * HH];
__device__ __nv_bfloat16 g_hlo[BB * HH];
__device__ __nv_bfloat16 g_xhi[BB * HH];
__device__ __nv_bfloat16 g_xlo[BB * HH];

__device__ __forceinline__ float sigmoidf_(float x) { return 1.0f / (1.0f + expf(-x)); }

// ---------------- mma.sync + cp.async helpers ------------------------------
__device__ __forceinline__ uint32_t smem_u32(const void* p) {
    uint32_t a;
    asm("{ .reg .u64 t; cvta.to.shared.u64 t, %1; cvt.u32.u64 %0, t; }" : "=r"(a) : "l"(p));
    return a;
}
__device__ __forceinline__ void cpasync16(uint32_t saddr, const void* g) {
    asm volatile("cp.async.cg.shared.global [%0], [%1], 16;" :: "r"(saddr), "l"(g));
}
#define CP_COMMIT() asm volatile("cp.async.commit_group;" ::: "memory")
#define CP_WAIT1()  asm volatile("cp.async.wait_group 1;" ::: "memory")
#define CP_WAIT0()  asm volatile("cp.async.wait_group 0;" ::: "memory")

__device__ __forceinline__ void ldmA(uint32_t base, int R0, int kk0, int lane, uint32_t* a) {
    int mat = lane >> 3, ri = lane & 7;
    uint32_t addr = base + (uint32_t)(R0 + ri + ((mat & 1) << 3)) * 80u
                         + (uint32_t)((kk0 + ((mat >> 1) << 3)) << 1);
    asm volatile("ldmatrix.sync.aligned.m8n8.x4.shared.b16 {%0,%1,%2,%3}, [%4];"
        : "=r"(a[0]), "=r"(a[1]), "=r"(a[2]), "=r"(a[3]) : "r"(addr));
}
__device__ __forceinline__ void ldmB(uint32_t base, int N0, int kk0, int lane, uint32_t* b) {
    int mat = lane >> 3, ri = lane & 7;
    uint32_t addr = base + (uint32_t)(N0 + ri + ((mat >> 1) << 3)) * 80u
                         + (uint32_t)((kk0 + ((mat & 1) << 3)) << 1);
    asm volatile("ldmatrix.sync.aligned.m8n8.x4.shared.b16 {%0,%1,%2,%3}, [%4];"
        : "=r"(b[0]), "=r"(b[1]), "=r"(b[2]), "=r"(b[3]) : "r"(addr));
}
__device__ __forceinline__ void mma16816(float* d, const uint32_t* a, const uint32_t* b) {
    asm volatile("mma.sync.aligned.m16n8k16.row.col.f32.bf16.bf16.f32 "
        "{%0,%1,%2,%3}, {%4,%5,%6,%7}, {%8,%9}, {%0,%1,%2,%3};"
        : "+f"(d[0]), "+f"(d[1]), "+f"(d[2]), "+f"(d[3])
        : "r"(a[0]), "r"(a[1]), "r"(a[2]), "r"(a[3]), "r"(b[0]), "r"(b[1]));
}

#define SA_HI 0
#define SA_LO 10240
#define SB_HI 20480
#define SB_LO 25600
#define BUF_BYTES 30720
#define DSMEM (2 * BUF_BYTES)

struct Frag { float acc[2][4][4]; };

// issue cp.async loads for one BK=32 chunk into buf
__device__ __forceinline__ void load_chunk(char* buf,
    const __nv_bfloat16* Ahi, const __nv_bfloat16* Alo, size_t arow0,
    const __nv_bfloat16* Bhi, const __nv_bfloat16* Blo, const int* btok,
    int k0, int tid)
{
    uint32_t sb = smem_u32(buf);
#pragma unroll
    for (int q0 = 0; q0 < 512; q0 += 256) {
        int q = q0 + tid;
        int r = q >> 2, u = q & 3;
        size_t off = (arow0 + (size_t)r * HH + k0) * 2 + (size_t)u * 16;
        cpasync16(sb + SA_HI + r * 80 + u * 16, (const char*)Ahi + off);
        cpasync16(sb + SA_LO + r * 80 + u * 16, (const char*)Alo + off);
    }
    {
        int r = tid >> 2, u = tid & 3;
        size_t row = btok ? (size_t)btok[r] : (size_t)r;
        size_t off = (row * HH + k0) * 2 + (size_t)u * 16;
        cpasync16(sb + SB_HI + r * 80 + u * 16, (const char*)Bhi + off);
        cpasync16(sb + SB_LO + r * 80 + u * 16, (const char*)Blo + off);
    }
}

// ldmatrix + 3-term split MMAs on one ready buffer
__device__ __forceinline__ void compute_chunk(char* buf, int lane, int wm, int wn, Frag& f)
{
    uint32_t sb = smem_u32(buf);
#pragma unroll
    for (int ks = 0; ks < 32; ks += 16) {
        uint32_t ahi[2][4], alo[2][4];
        ldmA(sb + SA_HI, wm * 32,      ks, lane, ahi[0]);
        ldmA(sb + SA_HI, wm * 32 + 16, ks, lane, ahi[1]);
        ldmA(sb + SA_LO, wm * 32,      ks, lane, alo[0]);
        ldmA(sb + SA_LO, wm * 32 + 16, ks, lane, alo[1]);
        uint32_t bhi[8], blo[8];
        ldmB(sb + SB_HI, wn * 32,      ks, lane, bhi);
        ldmB(sb + SB_HI, wn * 32 + 16, ks, lane, bhi + 4);
        ldmB(sb + SB_LO, wn * 32,      ks, lane, blo);
        ldmB(sb + SB_LO, wn * 32 + 16, ks, lane, blo + 4);
#pragma unroll
        for (int i = 0; i < 2; i++)
#pragma unroll
            for (int j = 0; j < 4; j++) {
                mma16816(f.acc[i][j], ahi[i], bhi + j * 2);
                mma16816(f.acc[i][j], ahi[i], blo + j * 2);
                mma16816(f.acc[i][j], alo[i], bhi + j * 2);
            }
    }
}

// full pipelined GEMM mainloop over nch chunks starting at kbase
__device__ __forceinline__ void gemm_pipeline(char* dynbuf,
    const __nv_bfloat16* Ahi, const __nv_bfloat16* Alo, size_t arow0,
    const __nv_bfloat16* Bhi, const __nv_bfloat16* Blo, const int* btok,
    int kbase, int nch, int tid, int lane, int wm, int wn, Frag& f)
{
#pragma unroll
    for (int i = 0; i < 2; i++)
#pragma unroll
        for (int j = 0; j < 4; j++)
#pragma unroll
            for (int q = 0; q < 4; q++) f.acc[i][j][q] = 0.0f;

    char* bufs[2] = { dynbuf, dynbuf + BUF_BYTES };
    load_chunk(bufs[0], Ahi, Alo, arow0, Bhi, Blo, btok, kbase, tid);
    CP_COMMIT();
    for (int ch = 0; ch < nch; ch++) {
        if (ch + 1 < nch) {
            load_chunk(bufs[(ch + 1) & 1], Ahi, Alo, arow0, Bhi, Blo, btok,
                       kbase + (ch + 1) * 32, tid);
            CP_COMMIT();
            CP_WAIT1();
        } else {
            CP_WAIT0();
        }
        __syncthreads();
        compute_chunk(bufs[ch & 1], lane, wm, wn, f);
        __syncthreads();
    }
}

// epilogue: transpose via smem, then coalesced f(v)-major stores
template <typename StoreFn>
__device__ __forceinline__ void epilogue(char* dynbuf, int wid, int lane, Frag& f, StoreFn store)
{
    float* F = (float*)dynbuf;
    for (int phase = 0; phase < 2; phase++) {
        __syncthreads();
        if ((wid >> 2) == phase) {
            float* R = F + (wid & 3) * (32 * 33);
            int row = lane >> 2, cp = (lane & 3) * 2;
#pragma unroll
            for (int i = 0; i < 2; i++)
#pragma unroll
                for (int j = 0; j < 4; j++) {
                    R[(j * 8 + cp)     * 33 + i * 16 + row]     = f.acc[i][j][0];
                    R[(j * 8 + cp + 1) * 33 + i * 16 + row]     = f.acc[i][j][1];
                    R[(j * 8 + cp)     * 33 + i * 16 + row + 8] = f.acc[i][j][2];
                    R[(j * 8 + cp + 1) * 33 + i * 16 + row + 8] = f.acc[i][j][3];
                }
            __syncwarp();
            store(R);
        }
    }
}

// ---------------- tiny prep kernels ----------------
__global__ void k_len(const int* __restrict__ ids) {
    __shared__ int cnt[4];
    int b = blockIdx.x;
    int nz = (ids[b * SS + threadIdx.x] != 0) ? 1 : 0;
    unsigned m = __ballot_sync(0xffffffffu, nz);
    if ((threadIdx.x & 31) == 0) cnt[threadIdx.x >> 5] = __popc(m);
    __syncthreads();
    if (threadIdx.x == 0) g_len[b] = cnt[0] + cnt[1] + cnt[2] + cnt[3];
}

__global__ void k_zero() {
    int i = blockIdx.x * 256 + threadIdx.x;
    g_c[i] = 0.0f;
    g_hhi[i] = __float2bfloat16(0.0f);
    g_hlo[i] = __float2bfloat16(0.0f);
}

// bf16 split of a weight matrix
__global__ void k_split(int sel, const float* __restrict__ src) {
    size_t n, nsrc;
    __nv_bfloat16 *hi, *lo;
    if (sel == 0)      { hi = g_Whi;   lo = g_Wlo;   n = (size_t)VP * HH; nsrc = (size_t)VV * HH; }
    else if (sel == 1) { hi = g_embHi; lo = g_embLo; n = (size_t)VV * HH; nsrc = n; }
    else if (sel == 2) { hi = g_WihHi; lo = g_WihLo; n = (size_t)GG * HH; nsrc = n; }
    else               { hi = g_WhhHi; lo = g_WhhLo; n = (size_t)GG * HH; nsrc = n; }
    for (size_t i = (size_t)blockIdx.x * blockDim.x + threadIdx.x; i < n;
         i += (size_t)gridDim.x * blockDim.x) {
        float w = (i < nsrc) ? src[i] : 0.0f;
        __nv_bfloat16 h = __float2bfloat16(w);
        hi[i] = h;
        lo[i] = __float2bfloat16(w - __bfloat162float(h));
    }
}

// ---------------- HMMA embed: Xg[m, j] = emb[tok_m] @ W_ih^T + biases ------
__global__ __launch_bounds__(256) void k_embed_hmma(
    const int* __restrict__ ids, const float* __restrict__ b_ih,
    const float* __restrict__ b_hh)
{
    extern __shared__ char dynbuf[];
    __shared__ int toks[64];
    const int tid = threadIdx.x;
    const int wid = tid >> 5;
    const int lane = tid & 31;
    const int wm = wid & 3, wn = wid >> 2;
    const int j0 = blockIdx.x * 128;
    const int n0 = blockIdx.y * 64;

    if (tid < 64) {
        int m = n0 + tid;
        toks[tid] = ids[(m & 63) * SS + (m >> 6)];
    }
    __syncthreads();

    Frag f;
    gemm_pipeline(dynbuf, g_WihHi, g_WihLo, (size_t)j0 * HH,
                  g_embHi, g_embLo, toks, 0, 32, tid, lane, wm, wn, f);

    epilogue(dynbuf, wid, lane, f, [&](float* R) {
        int j = j0 + wm * 32 + lane;
        float bias = b_ih[j] + b_hh[j];
#pragma unroll 8
        for (int bb = 0; bb < 32; bb++) {
            int m = n0 + wn * 32 + bb;
            g_Xg[(size_t)m * GG + j] = R[bb * 33 + lane] + bias;
        }
    });
}

// ---------------- HMMA gates -----------------------------------------------
// mode 0 (prompt): grid (32, 4): W_hh x h -> parts 0..3 (K-slices of 256)
// mode 1 (decode): grid (32, 8): y<4: W_ih x x -> parts 0..3; y>=4: W_hh x h -> 4..7
__global__ __launch_bounds__(256) void k_gates_hmma(int mode)
{
    extern __shared__ char dynbuf[];
    const int tid = threadIdx.x;
    const int wid = tid >> 5;
    const int lane = tid & 31;
    const int wm = wid & 3, wn = wid >> 2;
    const int j0 = blockIdx.x * 128;
    const int half = (mode == 1 && blockIdx.y >= 4) ? 1 : 0;
    const int kslot = blockIdx.y & 3;
    const __nv_bfloat16 *Ahi, *Alo, *Bhi, *Blo;
    if (mode == 0 || half == 1) { Ahi = g_WhhHi; Alo = g_WhhLo; Bhi = g_hhi; Blo = g_hlo; }
    else                        { Ahi = g_WihHi; Alo = g_WihLo; Bhi = g_xhi; Blo = g_xlo; }
    const int part = (mode == 0) ? kslot : (half * 4 + kslot);
    float* out = g_part + (size_t)part * (BB * GG);

    Frag f;
    gemm_pipeline(dynbuf, Ahi, Alo, (size_t)j0 * HH,
                  Bhi, Blo, nullptr, kslot * 256, 8, tid, lane, wm, wn, f);

    epilogue(dynbuf, wid, lane, f, [&](float* R) {
        int j = j0 + wm * 32 + lane;
#pragma unroll 8
        for (int bb = 0; bb < 32; bb++) {
            int b = wn * 32 + bb;
            out[(size_t)b * GG + j] = R[bb * 33 + lane];
        }
    });
}

// ---------------- gate combine + state update ------------------------------
__global__ void k_update(int s, int nparts,
                         const float* __restrict__ bi, const float* __restrict__ bh)
{
    int idx = blockIdx.x * blockDim.x + threadIdx.x;
    int b = idx >> 10;
    int hc = idx & 1023;
    bool valid = (s < 0) || (s < g_len[b]);
    if (!valid) return;
    const float* xadd = (s >= 0) ? (g_Xg + (size_t)s * BB * GG) : nullptr;

    float g4[4];
#pragma unroll
    for (int gi = 0; gi < 4; gi++) {
        int j = gi * HH + hc;
        float v = xadd ? xadd[(size_t)b * GG + j] : (bi[j] + bh[j]);
#pragma unroll
        for (int p = 0; p < 8; p++)
            if (p < nparts) v += g_part[(size_t)p * BB * GG + (size_t)b * GG + j];
        g4[gi] = v;
    }
    float ig = sigmoidf_(g4[0]);
    float fg = sigmoidf_(g4[1]);
    float gg = tanhf(g4[2]);
    float og = sigmoidf_(g4[3]);
    float cn = fg * g_c[idx] + ig * gg;
    float hn = og * tanhf(cn);
    g_c[idx] = cn;
    __nv_bfloat16 hi = __float2bfloat16(hn);
    g_hhi[idx] = hi;
    g_hlo[idx] = __float2bfloat16(hn - __bfloat162float(hi));
}

// ---------------- HMMA logits ----------------------------------------------
__global__ __launch_bounds__(256) void k_logits_mma(
    const float* __restrict__ b_fc, float* __restrict__ outbuf, int t)
{
    extern __shared__ char dynbuf[];
    const int tid = threadIdx.x;
    const int wid = tid >> 5;
    const int lane = tid & 31;
    const int wm = wid & 3, wn = wid >> 2;
    const int v0 = blockIdx.x * 128;

    Frag f;
    gemm_pipeline(dynbuf, g_Whi, g_Wlo, (size_t)v0 * HH,
                  g_hhi, g_hlo, nullptr, 0, 32, tid, lane, wm, wn, f);

    epilogue(dynbuf, wid, lane, f, [&](float* R) {
        int v = v0 + wm * 32 + lane;
        if (v < VV) {
            float bias = b_fc[v];
#pragma unroll 8
            for (int bb = 0; bb < 32; bb++) {
                int b = wn * 32 + bb;
                outbuf[((size_t)b * TT + t) * VV + v] = R[bb * 33 + lane] + bias;
            }
        }
    });
}

// ---------------- argmax (first-max tie-break) -----------------------------
__global__ void k_argmax_part(const float* __restrict__ outbuf, int t) {
    __shared__ float sv[256];
    __shared__ int   si[256];
    int b = blockIdx.y;
    const float* row = outbuf + ((size_t)b * TT + t) * VV;
    int chunk = (VV + 31) / 32;
    int start = blockIdx.x * chunk;
    int end = min(start + chunk, VV);
    float best = -3.4e38f; int bi = VV;
    for (int v = start + threadIdx.x; v < end; v += 256) {
        float x = row[v];
        if (x > best || (x == best && v < bi)) { best = x; bi = v; }
    }
    sv[threadIdx.x] = best; si[threadIdx.x] = bi;
    __syncthreads();
    for (int st = 128; st > 0; st >>= 1) {
        if (threadIdx.x < st) {
            float o = sv[threadIdx.x + st]; int oi = si[threadIdx.x + st];
            if (o > sv[threadIdx.x] || (o == sv[threadIdx.x] && oi < si[threadIdx.x])) {
                sv[threadIdx.x] = o; si[threadIdx.x] = oi;
            }
        }
        __syncthreads();
    }
    if (threadIdx.x == 0) { g_pv[b * 32 + blockIdx.x] = sv[0]; g_pi[b * 32 + blockIdx.x] = si[0]; }
}

__global__ void k_argmax_fin() {
    __shared__ float sv[32];
    __shared__ int   si[32];
    __shared__ int   stok;
    int b = blockIdx.x;
    if (threadIdx.x < 32) { sv[threadIdx.x] = g_pv[b * 32 + threadIdx.x]; si[threadIdx.x] = g_pi[b * 32 + threadIdx.x]; }
    __syncthreads();
    if (threadIdx.x == 0) {
        float best = sv[0]; int bi = si[0];
        for (int q = 1; q < 32; q++)
            if (sv[q] > best || (sv[q] == best && si[q] < bi)) { best = sv[q]; bi = si[q]; }
        stok = bi;
    }
    __syncthreads();
    size_t tok = (size_t)stok;
    ((uint2*)(g_xhi + (size_t)b * HH))[threadIdx.x] = ((const uint2*)(g_embHi + tok * HH))[threadIdx.x];
    ((uint2*)(g_xlo + (size_t)b * HH))[threadIdx.x] = ((const uint2*)(g_embLo + tok * HH))[threadIdx.x];
}

// ---------------- driver ----------------
extern "C" void kernel_launch(void* const* d_in, const int* in_sizes, int n_in,
                              void* d_out, int out_size)
{
    const int*   ids  = (const int*)d_in[0];
    const float* emb  = (const float*)d_in[2];
    const float* W_ih = (const float*)d_in[3];
    const float* W_hh = (const float*)d_in[4];
    const float* b_ih = (const float*)d_in[5];
    const float* b_hh = (const float*)d_in[6];
    const float* W_fc = (const float*)d_in[7];
    const float* b_fc = (const float*)d_in[8];
    float* out = (float*)d_out;

    static bool attr_done = false;
    if (!attr_done) {
        cudaFuncSetAttribute(k_embed_hmma, cudaFuncAttributeMaxDynamicSharedMemorySize, DSMEM);
        cudaFuncSetAttribute(k_gates_hmma, cudaFuncAttributeMaxDynamicSharedMemorySize, DSMEM);
        cudaFuncSetAttribute(k_logits_mma, cudaFuncAttributeMaxDynamicSharedMemorySize, DSMEM);
        attr_done = true;
    }

    k_len<<<BB, 128>>>(ids);
    k_zero<<<(BB * HH) / 256, 256>>>();
    k_split<<<2048, 256>>>(0, W_fc);
    k_split<<<2048, 256>>>(1, emb);
    k_split<<<512, 256>>>(2, W_ih);
    k_split<<<512, 256>>>(3, W_hh);

    k_embed_hmma<<<dim3(GG / 128, (BB * SS) / 64), 256, DSMEM>>>(ids, b_ih, b_hh);

    for (int s = 0; s < SS; s++) {
        k_gates_hmma<<<dim3(32, 4), 256, DSMEM>>>(0);
        k_update<<<(BB * HH) / 256, 256>>>(s, 4, b_ih, b_hh);
    }

    const int vgrid = (VV + 127) / 128;   // 393
    k_logits_mma<<<vgrid, 256, DSMEM>>>(b_fc, out, 0);

    for (int t = 1; t < TT; t++) {
        k_argmax_part<<<dim3(32, BB), 256>>>(out, t - 1);
        k_argmax_fin<<<BB, 256>>>();
        k_gates_hmma<<<dim3(32, 8), 256, DSMEM>>>(1);
        k_update<<<(BB * HH) / 256, 256>>>(-1, 8, b_ih, b_hh);
        k_logits_mma<<<vgrid, 256, DSMEM>>>(b_fc, out, t);
    }
}